// round 2
// baseline (speedup 1.0000x reference)
#include <cuda_runtime.h>
#include <math.h>

// Problem constants
#define HD   1024   // hidden dim
#define NB   16     // batch
#define SS   2048   // sequence length (== 2H)
#define TWOH 2048   // 2 * hidden

// ---------------- scratch (no allocations allowed) ----------------
__device__ float g_rowsum[TWOH];                 // sum_j W1[i,j]
__device__ float g_partial[NB * 16 * HD];        // [b][iblk(16)][s(1024)] GEMM-epilogue partials
__device__ float g_score[NB * SS];               // [b][2048]
__device__ float g_attn[NB * SS];                // softmax weights
__device__ float g_outpart[NB * 8 * HD];         // [b][schunk(8)][h]

// ---------------- K0: rowsum of W1 ----------------
__global__ __launch_bounds__(256) void rowsum_kernel(const float* __restrict__ W1) {
    int i = blockIdx.x;                // 2048 rows
    const float* row = W1 + (size_t)i * TWOH;
    float s = 0.f;
    for (int j = threadIdx.x; j < TWOH; j += blockDim.x) s += row[j];
    __shared__ float sm[256];
    sm[threadIdx.x] = s;
    __syncthreads();
    for (int o = 128; o; o >>= 1) {
        if (threadIdx.x < o) sm[threadIdx.x] += sm[threadIdx.x + o];
        __syncthreads();
    }
    if (threadIdx.x == 0) g_rowsum[i] = sm[0];
}

// ---------------- K1: right-half scores (the collapsed GEMM) ----------------
// The reference's raw reshape makes h[b, j, s] = dec[b, s-1024] for s >= 1024,
// independent of j. So wh[b,i,s>=1024] = tanh(rowsum(W1)[i] * dec[b,s-1024]),
// and the right half of the big einsum collapses to this rank-1 evaluation:
// score[b, 1024+sp] = sum_i w2[i] * tanh(rowsum[i] * dec[b, sp])
__global__ __launch_bounds__(256) void score2_kernel(const float* __restrict__ dec,
                                                     const float* __restrict__ w2) {
    int warp = (blockIdx.x * blockDim.x + threadIdx.x) >> 5;   // 16384 warps
    int lane = threadIdx.x & 31;
    int b  = warp >> 10;
    int sp = warp & 1023;
    float x = dec[b * HD + sp];
    float acc = 0.f;
    for (int i = lane; i < TWOH; i += 32)
        acc += w2[i] * tanhf(g_rowsum[i] * x);
#pragma unroll
    for (int o = 16; o; o >>= 1) acc += __shfl_xor_sync(0xFFFFFFFFu, acc, o);
    if (lane == 0) g_score[b * SS + HD + sp] = acc;
}

// ---------------- K2: main SGEMM G_b = W1 @ enc_b, fused w2*tanh reduction ----
// For s < 1024, h[b, j, s] = enc[b, j, s] (j = sequence index as K-dim).
// Block tile 128(M=i) x 128(N=s), BK=8, 256 threads, 8x8 per thread.
// G is never materialized: epilogue reduces w2[i]*tanh(G[i,s]) over the M tile.
#define BM 128
#define BN 128
#define BK 8
#define TM 8
#define TN 8

__global__ __launch_bounds__(256) void gemm_kernel(const float* __restrict__ W1,
                                                   const float* __restrict__ enc,
                                                   const float* __restrict__ w2) {
    int bx = blockIdx.x;   // N tile: 0..7  (s)
    int by = blockIdx.y;   // M tile: 0..15 (i)
    int b  = blockIdx.z;   // batch

    __shared__ float As[BK][BM];
    __shared__ float Bs[BK][BN];
    __shared__ float red[16][BN];

    int tid = threadIdx.x;
    int tx = tid & 15;     // 0..15 (n)
    int ty = tid >> 4;     // 0..15 (m)

    const float* A  = W1  + (size_t)(by * BM) * TWOH;
    const float* Bp = enc + (size_t)b * SS * HD + bx * BN;   // E_b[j, s], row stride HD

    int a_row  = tid >> 1;          // 0..127
    int a_col4 = (tid & 1) * 4;     // 0 or 4
    int b_row  = tid >> 5;          // 0..7
    int b_col4 = (tid & 31) * 4;    // 0..124

    float acc[TM][TN];
#pragma unroll
    for (int m = 0; m < TM; m++)
#pragma unroll
        for (int n = 0; n < TN; n++) acc[m][n] = 0.f;

    for (int k0 = 0; k0 < TWOH; k0 += BK) {
        float4 av = *(const float4*)(A + (size_t)a_row * TWOH + k0 + a_col4);
        As[a_col4 + 0][a_row] = av.x;
        As[a_col4 + 1][a_row] = av.y;
        As[a_col4 + 2][a_row] = av.z;
        As[a_col4 + 3][a_row] = av.w;
        float4 bv = *(const float4*)(Bp + (size_t)(k0 + b_row) * HD + b_col4);
        *(float4*)&Bs[b_row][b_col4] = bv;
        __syncthreads();

#pragma unroll
        for (int kk = 0; kk < BK; kk++) {
            float4 a0 = *(const float4*)&As[kk][ty * TM];
            float4 a1 = *(const float4*)&As[kk][ty * TM + 4];
            float4 b0 = *(const float4*)&Bs[kk][tx * TN];
            float4 b1 = *(const float4*)&Bs[kk][tx * TN + 4];
            float ra[TM] = {a0.x, a0.y, a0.z, a0.w, a1.x, a1.y, a1.z, a1.w};
            float rb[TN] = {b0.x, b0.y, b0.z, b0.w, b1.x, b1.y, b1.z, b1.w};
#pragma unroll
            for (int m = 0; m < TM; m++)
#pragma unroll
                for (int n = 0; n < TN; n++)
                    acc[m][n] += ra[m] * rb[n];
        }
        __syncthreads();
    }

    // Epilogue: per-column partial of sum_i w2[i]*tanh(G[i,s]) over this 128-row tile
    float w[TM];
#pragma unroll
    for (int m = 0; m < TM; m++) w[m] = w2[by * BM + ty * TM + m];

    float colp[TN];
#pragma unroll
    for (int n = 0; n < TN; n++) {
        float s = 0.f;
#pragma unroll
        for (int m = 0; m < TM; m++) s += w[m] * tanhf(acc[m][n]);
        colp[n] = s;
    }
#pragma unroll
    for (int n = 0; n < TN; n++) red[ty][tx * TN + n] = colp[n];
    __syncthreads();

    if (tid < BN) {
        float s = 0.f;
#pragma unroll
        for (int r = 0; r < 16; r++) s += red[r][tid];
        g_partial[((size_t)b * 16 + by) * HD + bx * BN + tid] = s;
    }
}

// ---------------- K3: reduce i-block partials into left-half scores ----------
__global__ __launch_bounds__(256) void reduce_partial_kernel() {
    int idx = blockIdx.x * blockDim.x + threadIdx.x;   // 16384
    int b = idx >> 10;
    int s = idx & 1023;
    float acc = 0.f;
#pragma unroll
    for (int ib = 0; ib < 16; ib++)
        acc += g_partial[((size_t)b * 16 + ib) * HD + s];
    g_score[b * SS + s] = acc;
}

// ---------------- K4: softmax over S per batch ----------------
__global__ __launch_bounds__(256) void softmax_kernel() {
    int b = blockIdx.x;
    int tid = threadIdx.x;        // 256
    __shared__ float sm[256];
    float* sc = g_score + b * SS;

    float m = -1e30f;
    for (int s = tid; s < SS; s += 256) m = fmaxf(m, sc[s]);
    sm[tid] = m;
    __syncthreads();
    for (int o = 128; o; o >>= 1) {
        if (tid < o) sm[tid] = fmaxf(sm[tid], sm[tid + o]);
        __syncthreads();
    }
    m = sm[0];
    __syncthreads();

    float sum = 0.f;
    for (int s = tid; s < SS; s += 256) {
        float e = expf(sc[s] - m);
        g_attn[b * SS + s] = e;
        sum += e;
    }
    sm[tid] = sum;
    __syncthreads();
    for (int o = 128; o; o >>= 1) {
        if (tid < o) sm[tid] += sm[tid + o];
        __syncthreads();
    }
    float inv = 1.0f / sm[0];
    for (int s = tid; s < SS; s += 256) g_attn[b * SS + s] *= inv;
}

// ---------------- K5: attention-weighted sum over enc (partials over s) ------
__global__ __launch_bounds__(256) void outpart_kernel(const float* __restrict__ enc) {
    int b  = blockIdx.y;          // 16
    int sc = blockIdx.x;          // 8 chunks of 256 s
    int s0 = sc * 256;
    int h0 = threadIdx.x * 4;     // 256 threads * 4 h = 1024

    const float* base = enc + ((size_t)b * SS + s0) * HD;
    const float* attn = g_attn + b * SS + s0;

    float ax = 0.f, ay = 0.f, az = 0.f, aw = 0.f;
#pragma unroll 4
    for (int s = 0; s < 256; s++) {
        float a = attn[s];
        float4 e = *(const float4*)(base + (size_t)s * HD + h0);
        ax += a * e.x; ay += a * e.y; az += a * e.z; aw += a * e.w;
    }
    float4 r = make_float4(ax, ay, az, aw);
    *(float4*)&g_outpart[((size_t)b * 8 + sc) * HD + h0] = r;
}

// ---------------- K6: final reduce over s-chunks ----------------
__global__ __launch_bounds__(256) void final_kernel(float* __restrict__ out) {
    int idx = blockIdx.x * blockDim.x + threadIdx.x;   // 16384
    int b = idx >> 10;
    int h = idx & 1023;
    float acc = 0.f;
#pragma unroll
    for (int c = 0; c < 8; c++)
        acc += g_outpart[((size_t)b * 8 + c) * HD + h];
    out[(size_t)b * HD + h] = acc;
}

// ---------------- launch ----------------
extern "C" void kernel_launch(void* const* d_in, const int* in_sizes, int n_in,
                              void* d_out, int out_size) {
    const float* enc = (const float*)d_in[0];   // [16, 2048, 1024]
    const float* dec = (const float*)d_in[1];   // [16, 1024]
    const float* W1  = (const float*)d_in[2];   // [2048, 2048]
    const float* w2  = (const float*)d_in[3];   // [1, 2048]
    float* out = (float*)d_out;                 // [16, 1024]

    rowsum_kernel<<<TWOH, 256>>>(W1);
    score2_kernel<<<2048, 256>>>(dec, w2);                 // 16384 warps
    gemm_kernel<<<dim3(8, 16, NB), 256>>>(W1, enc, w2);
    reduce_partial_kernel<<<64, 256>>>();
    softmax_kernel<<<NB, 256>>>();
    outpart_kernel<<<dim3(8, NB), 256>>>(enc);
    final_kernel<<<64, 256>>>(out);
}